// round 10
// baseline (speedup 1.0000x reference)
#include <cuda_runtime.h>
#include <cuda_fp16.h>
#include <cstdint>
#include <cstddef>

// ---------------- problem constants ----------------
namespace {
constexpr int kN1 = 67584;
constexpr int kN2 = 6144;
constexpr int kN3 = 1024;
constexpr int kFIN = 100;
constexpr int kHID = 256;
constexpr int kOUT = 47;
constexpr int kFAN2 = 10;
constexpr int kFAN3 = 5;
constexpr int K1P = 224;   // layer-1 K padded (agg 100 | dst 100 | zeros 24)
constexpr int K2P = 512;   // layer-2/3 K (agg 256 | dst 256)
}  // namespace

// ---------------- scratch (device globals) ----------------------------------
__device__ __half g_A1[(size_t)kN1 * K1P];
__device__ __half g_h1[(size_t)kN1 * kHID];
__device__ __half g_A2[(size_t)kN2 * K2P];
__device__ __half g_h2[(size_t)kN2 * kHID];
__device__ __half g_A3[(size_t)kN3 * K2P];
__device__ __half g_W1t[(size_t)256 * K1P];   // [N][K], transposed
__device__ __half g_W2t[(size_t)256 * K2P];
__device__ __half g_W3t[(size_t)64  * K2P];

// ---------------- PTX helpers ------------------------------------------------
__device__ __forceinline__ uint32_t smem_u32(const void* p) {
    uint32_t a;
    asm("{ .reg .u64 t; cvta.to.shared.u64 t, %1; cvt.u32.u64 %0, t; }" : "=r"(a) : "l"(p));
    return a;
}
__device__ __forceinline__ void cpasync16(uint32_t saddr, const void* g) {
    asm volatile("cp.async.cg.shared.global [%0], [%1], 16;" :: "r"(saddr), "l"(g) : "memory");
}
__device__ __forceinline__ void ldm_x4(uint32_t& r0, uint32_t& r1, uint32_t& r2, uint32_t& r3,
                                       uint32_t addr) {
    asm volatile("ldmatrix.sync.aligned.m8n8.x4.shared.b16 {%0,%1,%2,%3}, [%4];"
                 : "=r"(r0), "=r"(r1), "=r"(r2), "=r"(r3) : "r"(addr));
}
__device__ __forceinline__ void mma16816(float* c, const uint32_t* a, uint32_t b0, uint32_t b1) {
    asm volatile(
        "mma.sync.aligned.m16n8k16.row.col.f32.f16.f16.f32 "
        "{%0,%1,%2,%3}, {%4,%5,%6,%7}, {%8,%9}, {%0,%1,%2,%3};"
        : "+f"(c[0]), "+f"(c[1]), "+f"(c[2]), "+f"(c[3])
        : "r"(a[0]), "r"(a[1]), "r"(a[2]), "r"(a[3]), "r"(b0), "r"(b1));
}
__device__ __forceinline__ long long load_index(const void* p, long long i, int is64) {
    return is64 ? ((const long long*)p)[i] : (long long)((const int*)p)[i];
}
// dst1 = repeat(arange(N1), 15): element 15 as int64 equals 1 iff data is int64.
__device__ __forceinline__ int detect_is64(const void* dst1) {
    return (((const long long*)dst1)[15] == 1LL) ? 1 : 0;
}

// ---------------- pack weights (fp16, transposed [N][K]) ---------------------
__global__ void pack_weights(const float* __restrict__ Wl1, const float* __restrict__ Wr1,
                             const float* __restrict__ Wl2, const float* __restrict__ Wr2,
                             const float* __restrict__ Wl3, const float* __restrict__ Wr3) {
    int i = blockIdx.x * blockDim.x + threadIdx.x;
    if (i < 256 * K1P) {  // W1t (zeros for k >= 200)
        int n = i / K1P, k = i % K1P;
        float w = 0.f;
        if (k < kFIN) w = Wl1[k * kHID + n];
        else if (k < 2 * kFIN) w = Wr1[(k - kFIN) * kHID + n];
        g_W1t[i] = __float2half_rn(w);
    }
    if (i < 256 * K2P) {  // W2t
        int n = i / K2P, k = i % K2P;
        float w = (k < kHID) ? Wl2[k * kHID + n] : Wr2[(k - kHID) * kHID + n];
        g_W2t[i] = __float2half_rn(w);
    }
    if (i < 64 * K2P) {  // W3t (N padded 47 -> 64)
        int n = i / K2P, k = i % K2P;
        float w = 0.f;
        if (n < kOUT) w = (k < kHID) ? Wl3[k * kOUT + n] : Wr3[(k - kHID) * kOUT + n];
        g_W3t[i] = __float2half_rn(w);
    }
}

// ---------------- layer-1 aggregation: 1 node/warp, 5-deep MLP batch ---------
__global__ void __launch_bounds__(256, 5) agg1_kernel(
    const float* __restrict__ x, const void* __restrict__ src,
    const void* __restrict__ dst1) {
    int gw = (blockIdx.x * blockDim.x + threadIdx.x) >> 5;   // warp id = node
    int lane = threadIdx.x & 31;
    if (gw >= kN1) return;
    const int is64 = detect_is64(dst1);

    long long idx = 0;
    if (lane < 15) idx = load_index(src, (long long)gw * 15 + lane, is64);

    const float4* x4 = (const float4*)x;  // 25 float4 per x-row
    float4 acc = make_float4(0.f, 0.f, 0.f, 0.f);
#pragma unroll
    for (int jb = 0; jb < 3; ++jb) {
        float4 u[5];
#pragma unroll
        for (int t = 0; t < 5; ++t) {
            long long r0 = __shfl_sync(0xffffffffu, idx, jb * 5 + t);
            if (lane < 25) u[t] = __ldg(&x4[r0 * 25 + lane]);
        }
        if (lane < 25) {
#pragma unroll
            for (int t = 0; t < 5; ++t) {
                acc.x += u[t].x; acc.y += u[t].y; acc.z += u[t].z; acc.w += u[t].w;
            }
        }
    }
    const float inv = 1.0f / 15.0f;
    __half* o = g_A1 + (size_t)gw * K1P;
    if (lane < 25) {
        __half2 p0 = __floats2half2_rn(acc.x * inv, acc.y * inv);
        __half2 p1 = __floats2half2_rn(acc.z * inv, acc.w * inv);
        uint2 pk;
        pk.x = *(uint32_t*)&p0; pk.y = *(uint32_t*)&p1;
        *(uint2*)(o + 4 * lane) = pk;
        float4 d = __ldg(&x4[(size_t)gw * 25 + lane]);
        __half2 q0 = __floats2half2_rn(d.x, d.y);
        __half2 q1 = __floats2half2_rn(d.z, d.w);
        uint2 qk;
        qk.x = *(uint32_t*)&q0; qk.y = *(uint32_t*)&q1;
        *(uint2*)(o + kFIN + 4 * lane) = qk;
    }
    if (lane < 6) {  // zero-pad cols 200..223
        *(uint2*)(o + 200 + 4 * lane) = make_uint2(0u, 0u);
    }
}

// ---------------- 256-wide fp16 aggregation (layers 2,3) — plain loop --------
// (Round-4 form: regs 32, high occupancy — measured fastest.)
template <int FAN>
__global__ void agg256_kernel(const __half* __restrict__ h, const void* __restrict__ src,
                              __half* __restrict__ A, int ndst,
                              const void* __restrict__ dst1) {
    int gw = (blockIdx.x * blockDim.x + threadIdx.x) >> 5;
    int lane = threadIdx.x & 31;
    if (gw >= ndst) return;
    const int is64 = detect_is64(dst1);

    long long myidx = 0;
    if (lane < FAN) myidx = load_index(src, (long long)gw * FAN + lane, is64);

    const uint4* h4 = (const uint4*)h;  // 32 uint4 per row
    float acc[8];
#pragma unroll
    for (int t = 0; t < 8; ++t) acc[t] = 0.f;

#pragma unroll
    for (int j = 0; j < FAN; ++j) {
        long long rr = __shfl_sync(0xffffffffu, myidx, j);
        uint4 v = __ldg(&h4[rr * 32 + lane]);
        const __half2* hv = (const __half2*)&v;
#pragma unroll
        for (int q = 0; q < 4; ++q) {
            float2 f = __half22float2(hv[q]);
            acc[2 * q] += f.x;
            acc[2 * q + 1] += f.y;
        }
    }
    const float inv = 1.0f / (float)FAN;
    uint4 outv;
    __half2* ho = (__half2*)&outv;
#pragma unroll
    for (int q = 0; q < 4; ++q)
        ho[q] = __floats2half2_rn(acc[2 * q] * inv, acc[2 * q + 1] * inv);
    uint4* o = (uint4*)(A + (size_t)gw * K2P);
    o[lane] = outv;
    o[32 + lane] = __ldg(&h4[(size_t)gw * 32 + lane]);
}

// ---------------- HMMA GEMM: 3-stage cp.async pipeline, BK=32 ----------------
// out[M,Ntot] = A[M,K] @ Wt[Ntot,K]^T. 256 threads as WM x WN warps.
// Smem stride 40 fp16 (80 B): ldmatrix conflict-free. Dynamic smem:
//   [ A stages (3 x BM x 80B) | B stages (3 x BN x 80B) | bias BN x 4B ]
template <int BM, int BN, int WM, int WN, int KP, bool RELU, bool FINAL>
__global__ void __launch_bounds__(256, 2) mma_gemm(
    const __half* __restrict__ Ap, const __half* __restrict__ Wt,
    const float* __restrict__ bias, void* __restrict__ outv, int ntot) {
    constexpr int LDS = 40;
    constexpr int NIT = KP / 32;
    constexpr int NI = BN / WN / 8;
    static_assert(WM * WN == 8 && (NI & 1) == 0 && BM / WM == 32 && KP % 32 == 0, "cfg");

    extern __shared__ char smem[];
    const uint32_t sbase = smem_u32(smem);
    float* sbias = (float*)(smem + 3 * (BM + BN) * (LDS * 2));

    const int tid = threadIdx.x;
    const int wid = tid >> 5, lane = tid & 31;
    const int wm = wid % WM, wn = wid / WM;
    const int m0 = wm * 32;
    const int n0 = wn * (BN / WN);
    const size_t rowBase = (size_t)blockIdx.y * BM;
    const int colBase = blockIdx.x * BN;

    if (tid < BN) sbias[tid] = (colBase + tid < ntot) ? bias[colBase + tid] : 0.f;

    float acc[2][NI][4];
#pragma unroll
    for (int mi = 0; mi < 2; ++mi)
#pragma unroll
        for (int ni = 0; ni < NI; ++ni)
#pragma unroll
            for (int q = 0; q < 4; ++q) acc[mi][ni][q] = 0.f;

    auto aoff = [&](int s) { return sbase + (uint32_t)s * BM * (LDS * 2); };
    auto boff = [&](int s) { return sbase + 3u * BM * (LDS * 2) + (uint32_t)s * BN * (LDS * 2); };

    auto load_tile = [&](int it, int st) {
        const int k0 = it * 32;
        const __half* srcp = Ap + rowBase * KP + k0;
        const uint32_t ab = aoff(st);
#pragma unroll
        for (int t = 0; t < BM * 4 / 256; ++t) {   // BM x 32 fp16 = BM*4 chunks
            int c = tid + t * 256;
            int row = c >> 2, kc = c & 3;
            cpasync16(ab + row * (LDS * 2) + kc * 16, srcp + (size_t)row * KP + kc * 8);
        }
        const __half* wsrc = Wt + (size_t)colBase * KP + k0;
        const uint32_t bb = boff(st);
#pragma unroll
        for (int t = 0; t < BN * 4 / 256; ++t) {
            int c = tid + t * 256;
            int row = c >> 2, kc = c & 3;
            cpasync16(bb + row * (LDS * 2) + kc * 16, wsrc + (size_t)row * KP + kc * 8);
        }
        asm volatile("cp.async.commit_group;" ::: "memory");
    };

    load_tile(0, 0);
    load_tile(1, 1);
    for (int i = 0; i < NIT; ++i) {
        const int st = i % 3;
        if (i + 1 < NIT) {
            asm volatile("cp.async.wait_group 1;" ::: "memory");
        } else {
            asm volatile("cp.async.wait_group 0;" ::: "memory");
        }
        __syncthreads();

        const uint32_t aA = aoff(st);
        const uint32_t aB = boff(st);
#pragma unroll
        for (int kk = 0; kk < 2; ++kk) {
            uint32_t afr[2][4];
#pragma unroll
            for (int mi = 0; mi < 2; ++mi) {
                uint32_t ad = aA + (uint32_t)((m0 + mi * 16 + (lane & 15)) * (LDS * 2) +
                                              kk * 32 + (lane >> 4) * 16);
                ldm_x4(afr[mi][0], afr[mi][1], afr[mi][2], afr[mi][3], ad);
            }
            uint32_t bfr[NI][2];
#pragma unroll
            for (int p = 0; p < NI / 2; ++p) {  // pair of n8-tiles per ldmatrix.x4
                int row = n0 + p * 16 + ((lane >> 4) & 1) * 8 + (lane & 7);
                uint32_t bd = aB + (uint32_t)(row * (LDS * 2) +
                                              kk * 32 + ((lane >> 3) & 1) * 16);
                ldm_x4(bfr[2 * p][0], bfr[2 * p][1], bfr[2 * p + 1][0], bfr[2 * p + 1][1], bd);
            }
#pragma unroll
            for (int ni = 0; ni < NI; ++ni)
#pragma unroll
                for (int mi = 0; mi < 2; ++mi)
                    mma16816(acc[mi][ni], afr[mi], bfr[ni][0], bfr[ni][1]);
        }
        if (i + 2 < NIT) load_tile(i + 2, (i + 2) % 3);
    }

    const int r = lane >> 2;
    const int cp = (lane & 3) * 2;
#pragma unroll
    for (int mi = 0; mi < 2; ++mi) {
#pragma unroll
        for (int ni = 0; ni < NI; ++ni) {
            const int jc = n0 + ni * 8 + cp;
            const int col = colBase + jc;
            const size_t row0 = rowBase + m0 + mi * 16 + r;
            float v0 = acc[mi][ni][0] + sbias[jc];
            float v1 = acc[mi][ni][1] + sbias[jc + 1];
            float v2 = acc[mi][ni][2] + sbias[jc];
            float v3 = acc[mi][ni][3] + sbias[jc + 1];
            if (RELU) {
                v0 = fmaxf(v0, 0.f); v1 = fmaxf(v1, 0.f);
                v2 = fmaxf(v2, 0.f); v3 = fmaxf(v3, 0.f);
            }
            if (FINAL) {
                float* out = (float*)outv;
                if (col < ntot) {
                    out[row0 * ntot + col] = v0;
                    out[(row0 + 8) * ntot + col] = v2;
                }
                if (col + 1 < ntot) {
                    out[row0 * ntot + col + 1] = v1;
                    out[(row0 + 8) * ntot + col + 1] = v3;
                }
            } else {
                __half* out = (__half*)outv;
                *(__half2*)(out + row0 * ntot + col) = __floats2half2_rn(v0, v1);
                *(__half2*)(out + (row0 + 8) * ntot + col) = __floats2half2_rn(v2, v3);
            }
        }
    }
}

// ---------------- log_softmax over 47 cols, warp per row, in place -----------
__global__ void logsoftmax_kernel(float* __restrict__ out) {
    int gw = (blockIdx.x * blockDim.x + threadIdx.x) >> 5;
    int lane = threadIdx.x & 31;
    if (gw >= kN3) return;
    float* row = out + (long long)gw * kOUT;
    float v0 = (lane < kOUT) ? row[lane] : -1e30f;
    float v1 = (lane + 32 < kOUT) ? row[lane + 32] : -1e30f;
    float m = fmaxf(v0, v1);
#pragma unroll
    for (int o = 16; o; o >>= 1) m = fmaxf(m, __shfl_xor_sync(0xffffffffu, m, o));
    float s = 0.f;
    if (lane < kOUT) s += expf(v0 - m);
    if (lane + 32 < kOUT) s += expf(v1 - m);
#pragma unroll
    for (int o = 16; o; o >>= 1) s += __shfl_xor_sync(0xffffffffu, s, o);
    float lse = m + logf(s);
    if (lane < kOUT) row[lane] = v0 - lse;
    if (lane + 32 < kOUT) row[lane + 32] = v1 - lse;
}

// ---------------- launch -----------------------------------------------------
extern "C" void kernel_launch(void* const* d_in, const int* in_sizes, int n_in,
                              void* d_out, int out_size) {
    const float* x   = (const float*)d_in[0];
    const float* Wl1 = (const float*)d_in[1];
    const float* Wr1 = (const float*)d_in[2];
    const float* b1  = (const float*)d_in[3];
    const float* Wl2 = (const float*)d_in[4];
    const float* Wr2 = (const float*)d_in[5];
    const float* b2  = (const float*)d_in[6];
    const float* Wl3 = (const float*)d_in[7];
    const float* Wr3 = (const float*)d_in[8];
    const float* b3  = (const float*)d_in[9];
    const void*  src1 = d_in[10];
    const void*  dst1 = d_in[11];
    const void*  src2 = d_in[12];
    const void*  src3 = d_in[14];
    float* out = (float*)d_out;

    __half *A1, *A2, *A3, *W1t, *W2t, *W3t, *h1, *h2;
    cudaGetSymbolAddress((void**)&A1, g_A1);
    cudaGetSymbolAddress((void**)&A2, g_A2);
    cudaGetSymbolAddress((void**)&A3, g_A3);
    cudaGetSymbolAddress((void**)&W1t, g_W1t);
    cudaGetSymbolAddress((void**)&W2t, g_W2t);
    cudaGetSymbolAddress((void**)&W3t, g_W3t);
    cudaGetSymbolAddress((void**)&h1, g_h1);
    cudaGetSymbolAddress((void**)&h2, g_h2);

    constexpr int SM1 = 3 * (128 + 128) * 80 + 128 * 4;  // 61952
    constexpr int SM2 = 3 * (64 + 64) * 80 + 64 * 4;     // 30976
    cudaFuncSetAttribute((const void*)mma_gemm<128, 128, 4, 2, K1P, true, false>,
                         cudaFuncAttributeMaxDynamicSharedMemorySize, SM1);
    cudaFuncSetAttribute((const void*)mma_gemm<64, 64, 2, 4, K2P, true, false>,
                         cudaFuncAttributeMaxDynamicSharedMemorySize, SM2);
    cudaFuncSetAttribute((const void*)mma_gemm<64, 64, 2, 4, K2P, false, true>,
                         cudaFuncAttributeMaxDynamicSharedMemorySize, SM2);

    // Side stream for pack_weights overlap (created once on the uncaptured
    // correctness call; identical work every call).
    static cudaStream_t s1 = nullptr;
    static cudaEvent_t evF = nullptr, evW = nullptr;
    if (s1 == nullptr) {
        cudaStreamCreateWithFlags(&s1, cudaStreamNonBlocking);
        cudaEventCreateWithFlags(&evF, cudaEventDisableTiming);
        cudaEventCreateWithFlags(&evW, cudaEventDisableTiming);
    }

    // Fork: pack_weights on s1, agg1 on stream 0 (independent — is64 is
    // derived inline from dst1 inside the gather kernels).
    cudaEventRecord(evF, 0);
    cudaStreamWaitEvent(s1, evF, 0);
    pack_weights<<<512, 256, 0, s1>>>(Wl1, Wr1, Wl2, Wr2, Wl3, Wr3);
    cudaEventRecord(evW, s1);

    agg1_kernel<<<kN1 / 8, 256>>>(x, src1, dst1);
    cudaStreamWaitEvent(0, evW, 0);  // join before gemm1 needs W1t

    mma_gemm<128, 128, 4, 2, K1P, true, false>
        <<<dim3(2, kN1 / 128), 256, SM1>>>(A1, W1t, b1, h1, 256);

    // layer 2 (BN=64 -> 384 CTAs)
    agg256_kernel<kFAN2><<<kN2 / 8, 256>>>(h1, src2, A2, kN2, dst1);
    mma_gemm<64, 64, 2, 4, K2P, true, false>
        <<<dim3(4, kN2 / 64), 256, SM2>>>(A2, W2t, b2, h2, 256);

    // layer 3 -> d_out logits
    agg256_kernel<kFAN3><<<kN3 / 8, 256>>>(h2, src3, A3, kN3, dst1);
    mma_gemm<64, 64, 2, 4, K2P, false, true>
        <<<dim3(1, kN3 / 64), 256, SM2>>>(A3, W3t, b3, out, kOUT);

    // log_softmax in place
    logsoftmax_kernel<<<kN3 / 8, 256>>>(out);
}

// round 11
// speedup vs baseline: 1.0129x; 1.0129x over previous
#include <cuda_runtime.h>
#include <cuda_fp16.h>
#include <cstdint>
#include <cstddef>

// ---------------- problem constants ----------------
namespace {
constexpr int kN1 = 67584;
constexpr int kN2 = 6144;
constexpr int kN3 = 1024;
constexpr int kFIN = 100;
constexpr int kHID = 256;
constexpr int kOUT = 47;
constexpr int kFAN2 = 10;
constexpr int kFAN3 = 5;
constexpr int K1P = 224;   // layer-1 K padded (agg 100 | dst 100 | zeros 24)
constexpr int K2P = 512;   // layer-2/3 K (agg 256 | dst 256)
}  // namespace

// ---------------- scratch (device globals) ----------------------------------
__device__ __half g_A1[(size_t)kN1 * K1P];
__device__ __half g_h1[(size_t)kN1 * kHID];
__device__ __half g_A2[(size_t)kN2 * K2P];
__device__ __half g_h2[(size_t)kN2 * kHID];
__device__ __half g_A3[(size_t)kN3 * K2P];
__device__ __half g_W1t[(size_t)256 * K1P];   // [N][K], transposed
__device__ __half g_W2t[(size_t)256 * K2P];
__device__ __half g_W3t[(size_t)64  * K2P];

// ---------------- PTX helpers ------------------------------------------------
__device__ __forceinline__ uint32_t smem_u32(const void* p) {
    uint32_t a;
    asm("{ .reg .u64 t; cvta.to.shared.u64 t, %1; cvt.u32.u64 %0, t; }" : "=r"(a) : "l"(p));
    return a;
}
__device__ __forceinline__ void cpasync16(uint32_t saddr, const void* g) {
    asm volatile("cp.async.cg.shared.global [%0], [%1], 16;" :: "r"(saddr), "l"(g) : "memory");
}
__device__ __forceinline__ void ldm_x4(uint32_t& r0, uint32_t& r1, uint32_t& r2, uint32_t& r3,
                                       uint32_t addr) {
    asm volatile("ldmatrix.sync.aligned.m8n8.x4.shared.b16 {%0,%1,%2,%3}, [%4];"
                 : "=r"(r0), "=r"(r1), "=r"(r2), "=r"(r3) : "r"(addr));
}
__device__ __forceinline__ void mma16816(float* c, const uint32_t* a, uint32_t b0, uint32_t b1) {
    asm volatile(
        "mma.sync.aligned.m16n8k16.row.col.f32.f16.f16.f32 "
        "{%0,%1,%2,%3}, {%4,%5,%6,%7}, {%8,%9}, {%0,%1,%2,%3};"
        : "+f"(c[0]), "+f"(c[1]), "+f"(c[2]), "+f"(c[3])
        : "r"(a[0]), "r"(a[1]), "r"(a[2]), "r"(a[3]), "r"(b0), "r"(b1));
}
__device__ __forceinline__ long long load_index(const void* p, long long i, int is64) {
    return is64 ? ((const long long*)p)[i] : (long long)((const int*)p)[i];
}
// dst1 = repeat(arange(N1), 15): element 15 as int64 equals 1 iff data is int64.
__device__ __forceinline__ int detect_is64(const void* dst1) {
    return (((const long long*)dst1)[15] == 1LL) ? 1 : 0;
}

// ---------------- pack weights (fp16, transposed [N][K]) ---------------------
__global__ void pack_weights(const float* __restrict__ Wl1, const float* __restrict__ Wr1,
                             const float* __restrict__ Wl2, const float* __restrict__ Wr2,
                             const float* __restrict__ Wl3, const float* __restrict__ Wr3) {
    int i = blockIdx.x * blockDim.x + threadIdx.x;
    if (i < 256 * K1P) {  // W1t (zeros for k >= 200)
        int n = i / K1P, k = i % K1P;
        float w = 0.f;
        if (k < kFIN) w = Wl1[k * kHID + n];
        else if (k < 2 * kFIN) w = Wr1[(k - kFIN) * kHID + n];
        g_W1t[i] = __float2half_rn(w);
    }
    if (i < 256 * K2P) {  // W2t
        int n = i / K2P, k = i % K2P;
        float w = (k < kHID) ? Wl2[k * kHID + n] : Wr2[(k - kHID) * kHID + n];
        g_W2t[i] = __float2half_rn(w);
    }
    if (i < 64 * K2P) {  // W3t (N padded 47 -> 64)
        int n = i / K2P, k = i % K2P;
        float w = 0.f;
        if (n < kOUT) w = (k < kHID) ? Wl3[k * kOUT + n] : Wr3[(k - kHID) * kOUT + n];
        g_W3t[i] = __float2half_rn(w);
    }
}

// ---------------- layer-1 aggregation: cp.async gather into smem -------------
// Warp per node. 375 fire-and-forget cp.asyncs (15 edges x 25 16B chunks) into
// a 6 KB stage, ONE wait, then LDS reduction. No register MLP limit, no
// destination-register pressure -> high occupancy AND unbounded in-flight loads.
// Each lane reads back exactly the bytes it issued, so per-thread
// cp.async.wait_group(0) is sufficient (no syncwarp needed).
__global__ void __launch_bounds__(256) agg1_kernel(
    const float* __restrict__ x, const void* __restrict__ src,
    const void* __restrict__ dst1) {
    __shared__ __align__(16) char stage[8][15 * 400];   // 48000 B

    const int w = threadIdx.x >> 5, lane = threadIdx.x & 31;
    const long long node = (long long)blockIdx.x * 8 + w;
    const int is64 = detect_is64(dst1);

    long long idx = 0;
    if (lane < 15) idx = load_index(src, node * 15 + lane, is64);

    const float4* x4 = (const float4*)x;  // 25 float4 per x-row
    const uint32_t sb = smem_u32(&stage[w][0]);
#pragma unroll
    for (int j = 0; j < 15; ++j) {
        long long r = __shfl_sync(0xffffffffu, idx, j);
        if (lane < 25) cpasync16(sb + j * 400 + lane * 16, &x4[r * 25 + lane]);
    }
    asm volatile("cp.async.commit_group;" ::: "memory");

    // dst-row load overlaps the gather wait
    float4 d = make_float4(0.f, 0.f, 0.f, 0.f);
    if (lane < 25) d = __ldg(&x4[node * 25 + lane]);

    asm volatile("cp.async.wait_group 0;" ::: "memory");

    float4 acc = make_float4(0.f, 0.f, 0.f, 0.f);
    if (lane < 25) {
#pragma unroll
        for (int j = 0; j < 15; ++j) {
            float4 v = *(const float4*)(stage[w] + j * 400 + lane * 16);
            acc.x += v.x; acc.y += v.y; acc.z += v.z; acc.w += v.w;
        }
    }
    const float inv = 1.0f / 15.0f;
    __half* o = g_A1 + (size_t)node * K1P;
    if (lane < 25) {
        __half2 p0 = __floats2half2_rn(acc.x * inv, acc.y * inv);
        __half2 p1 = __floats2half2_rn(acc.z * inv, acc.w * inv);
        uint2 pk;
        pk.x = *(uint32_t*)&p0; pk.y = *(uint32_t*)&p1;
        *(uint2*)(o + 4 * lane) = pk;
        __half2 q0 = __floats2half2_rn(d.x, d.y);
        __half2 q1 = __floats2half2_rn(d.z, d.w);
        uint2 qk;
        qk.x = *(uint32_t*)&q0; qk.y = *(uint32_t*)&q1;
        *(uint2*)(o + kFIN + 4 * lane) = qk;
    }
    if (lane < 6) {  // zero-pad cols 200..223
        *(uint2*)(o + 200 + 4 * lane) = make_uint2(0u, 0u);
    }
}

// ---------------- 256-wide fp16 aggregation (layers 2,3): cp.async -----------
// Warp per node; FAN x 32 cp.asyncs (512 B rows) into smem stage, one wait,
// LDS reduction. Stage: 8 x FAN x 512 B.
template <int FAN>
__global__ void __launch_bounds__(256) agg256_kernel(
    const __half* __restrict__ h, const void* __restrict__ src,
    __half* __restrict__ A, int ndst, const void* __restrict__ dst1) {
    __shared__ __align__(16) char stage[8][FAN * 512];

    const int w = threadIdx.x >> 5, lane = threadIdx.x & 31;
    const long long node = (long long)blockIdx.x * 8 + w;
    const int is64 = detect_is64(dst1);

    long long idx = 0;
    if (lane < FAN) idx = load_index(src, node * FAN + lane, is64);

    const uint4* h4 = (const uint4*)h;  // 32 uint4 per row
    const uint32_t sb = smem_u32(&stage[w][0]);
#pragma unroll
    for (int j = 0; j < FAN; ++j) {
        long long r = __shfl_sync(0xffffffffu, idx, j);
        cpasync16(sb + j * 512 + lane * 16, &h4[r * 32 + lane]);
    }
    asm volatile("cp.async.commit_group;" ::: "memory");

    uint4 dcopy = __ldg(&h4[node * 32 + lane]);  // dst-row copy overlaps wait

    asm volatile("cp.async.wait_group 0;" ::: "memory");

    float acc[8];
#pragma unroll
    for (int t = 0; t < 8; ++t) acc[t] = 0.f;
#pragma unroll
    for (int j = 0; j < FAN; ++j) {
        uint4 v = *(const uint4*)(stage[w] + j * 512 + lane * 16);
        const __half2* hv = (const __half2*)&v;
#pragma unroll
        for (int q = 0; q < 4; ++q) {
            float2 f = __half22float2(hv[q]);
            acc[2 * q] += f.x;
            acc[2 * q + 1] += f.y;
        }
    }
    const float inv = 1.0f / (float)FAN;
    uint4 outv;
    __half2* ho = (__half2*)&outv;
#pragma unroll
    for (int q = 0; q < 4; ++q)
        ho[q] = __floats2half2_rn(acc[2 * q] * inv, acc[2 * q + 1] * inv);
    uint4* o = (uint4*)(A + (size_t)node * K2P);
    o[lane] = outv;
    o[32 + lane] = dcopy;
}

// ---------------- HMMA GEMM: 3-stage cp.async pipeline, BK=32 ----------------
// out[M,Ntot] = A[M,K] @ Wt[Ntot,K]^T. 256 threads as WM x WN warps.
// Smem stride 40 fp16 (80 B): ldmatrix conflict-free. Dynamic smem:
//   [ A stages (3 x BM x 80B) | B stages (3 x BN x 80B) | bias BN x 4B ]
template <int BM, int BN, int WM, int WN, int KP, bool RELU, bool FINAL>
__global__ void __launch_bounds__(256, 2) mma_gemm(
    const __half* __restrict__ Ap, const __half* __restrict__ Wt,
    const float* __restrict__ bias, void* __restrict__ outv, int ntot) {
    constexpr int LDS = 40;
    constexpr int NIT = KP / 32;
    constexpr int NI = BN / WN / 8;
    static_assert(WM * WN == 8 && (NI & 1) == 0 && BM / WM == 32 && KP % 32 == 0, "cfg");

    extern __shared__ char smem[];
    const uint32_t sbase = smem_u32(smem);
    float* sbias = (float*)(smem + 3 * (BM + BN) * (LDS * 2));

    const int tid = threadIdx.x;
    const int wid = tid >> 5, lane = tid & 31;
    const int wm = wid % WM, wn = wid / WM;
    const int m0 = wm * 32;
    const int n0 = wn * (BN / WN);
    const size_t rowBase = (size_t)blockIdx.y * BM;
    const int colBase = blockIdx.x * BN;

    if (tid < BN) sbias[tid] = (colBase + tid < ntot) ? bias[colBase + tid] : 0.f;

    float acc[2][NI][4];
#pragma unroll
    for (int mi = 0; mi < 2; ++mi)
#pragma unroll
        for (int ni = 0; ni < NI; ++ni)
#pragma unroll
            for (int q = 0; q < 4; ++q) acc[mi][ni][q] = 0.f;

    auto aoff = [&](int s) { return sbase + (uint32_t)s * BM * (LDS * 2); };
    auto boff = [&](int s) { return sbase + 3u * BM * (LDS * 2) + (uint32_t)s * BN * (LDS * 2); };

    auto load_tile = [&](int it, int st) {
        const int k0 = it * 32;
        const __half* srcp = Ap + rowBase * KP + k0;
        const uint32_t ab = aoff(st);
#pragma unroll
        for (int t = 0; t < BM * 4 / 256; ++t) {   // BM x 32 fp16 = BM*4 chunks
            int c = tid + t * 256;
            int row = c >> 2, kc = c & 3;
            cpasync16(ab + row * (LDS * 2) + kc * 16, srcp + (size_t)row * KP + kc * 8);
        }
        const __half* wsrc = Wt + (size_t)colBase * KP + k0;
        const uint32_t bb = boff(st);
#pragma unroll
        for (int t = 0; t < BN * 4 / 256; ++t) {
            int c = tid + t * 256;
            int row = c >> 2, kc = c & 3;
            cpasync16(bb + row * (LDS * 2) + kc * 16, wsrc + (size_t)row * KP + kc * 8);
        }
        asm volatile("cp.async.commit_group;" ::: "memory");
    };

    load_tile(0, 0);
    load_tile(1, 1);
    for (int i = 0; i < NIT; ++i) {
        const int st = i % 3;
        if (i + 1 < NIT) {
            asm volatile("cp.async.wait_group 1;" ::: "memory");
        } else {
            asm volatile("cp.async.wait_group 0;" ::: "memory");
        }
        __syncthreads();

        const uint32_t aA = aoff(st);
        const uint32_t aB = boff(st);
#pragma unroll
        for (int kk = 0; kk < 2; ++kk) {
            uint32_t afr[2][4];
#pragma unroll
            for (int mi = 0; mi < 2; ++mi) {
                uint32_t ad = aA + (uint32_t)((m0 + mi * 16 + (lane & 15)) * (LDS * 2) +
                                              kk * 32 + (lane >> 4) * 16);
                ldm_x4(afr[mi][0], afr[mi][1], afr[mi][2], afr[mi][3], ad);
            }
            uint32_t bfr[NI][2];
#pragma unroll
            for (int p = 0; p < NI / 2; ++p) {  // pair of n8-tiles per ldmatrix.x4
                int row = n0 + p * 16 + ((lane >> 4) & 1) * 8 + (lane & 7);
                uint32_t bd = aB + (uint32_t)(row * (LDS * 2) +
                                              kk * 32 + ((lane >> 3) & 1) * 16);
                ldm_x4(bfr[2 * p][0], bfr[2 * p][1], bfr[2 * p + 1][0], bfr[2 * p + 1][1], bd);
            }
#pragma unroll
            for (int ni = 0; ni < NI; ++ni)
#pragma unroll
                for (int mi = 0; mi < 2; ++mi)
                    mma16816(acc[mi][ni], afr[mi], bfr[ni][0], bfr[ni][1]);
        }
        if (i + 2 < NIT) load_tile(i + 2, (i + 2) % 3);
    }

    const int r = lane >> 2;
    const int cp = (lane & 3) * 2;
#pragma unroll
    for (int mi = 0; mi < 2; ++mi) {
#pragma unroll
        for (int ni = 0; ni < NI; ++ni) {
            const int jc = n0 + ni * 8 + cp;
            const int col = colBase + jc;
            const size_t row0 = rowBase + m0 + mi * 16 + r;
            float v0 = acc[mi][ni][0] + sbias[jc];
            float v1 = acc[mi][ni][1] + sbias[jc + 1];
            float v2 = acc[mi][ni][2] + sbias[jc];
            float v3 = acc[mi][ni][3] + sbias[jc + 1];
            if (RELU) {
                v0 = fmaxf(v0, 0.f); v1 = fmaxf(v1, 0.f);
                v2 = fmaxf(v2, 0.f); v3 = fmaxf(v3, 0.f);
            }
            if (FINAL) {
                float* out = (float*)outv;
                if (col < ntot) {
                    out[row0 * ntot + col] = v0;
                    out[(row0 + 8) * ntot + col] = v2;
                }
                if (col + 1 < ntot) {
                    out[row0 * ntot + col + 1] = v1;
                    out[(row0 + 8) * ntot + col + 1] = v3;
                }
            } else {
                __half* out = (__half*)outv;
                *(__half2*)(out + row0 * ntot + col) = __floats2half2_rn(v0, v1);
                *(__half2*)(out + (row0 + 8) * ntot + col) = __floats2half2_rn(v2, v3);
            }
        }
    }
}

// ---------------- log_softmax over 47 cols, warp per row, in place -----------
__global__ void logsoftmax_kernel(float* __restrict__ out) {
    int gw = (blockIdx.x * blockDim.x + threadIdx.x) >> 5;
    int lane = threadIdx.x & 31;
    if (gw >= kN3) return;
    float* row = out + (long long)gw * kOUT;
    float v0 = (lane < kOUT) ? row[lane] : -1e30f;
    float v1 = (lane + 32 < kOUT) ? row[lane + 32] : -1e30f;
    float m = fmaxf(v0, v1);
#pragma unroll
    for (int o = 16; o; o >>= 1) m = fmaxf(m, __shfl_xor_sync(0xffffffffu, m, o));
    float s = 0.f;
    if (lane < kOUT) s += expf(v0 - m);
    if (lane + 32 < kOUT) s += expf(v1 - m);
#pragma unroll
    for (int o = 16; o; o >>= 1) s += __shfl_xor_sync(0xffffffffu, s, o);
    float lse = m + logf(s);
    if (lane < kOUT) row[lane] = v0 - lse;
    if (lane + 32 < kOUT) row[lane + 32] = v1 - lse;
}

// ---------------- launch -----------------------------------------------------
extern "C" void kernel_launch(void* const* d_in, const int* in_sizes, int n_in,
                              void* d_out, int out_size) {
    const float* x   = (const float*)d_in[0];
    const float* Wl1 = (const float*)d_in[1];
    const float* Wr1 = (const float*)d_in[2];
    const float* b1  = (const float*)d_in[3];
    const float* Wl2 = (const float*)d_in[4];
    const float* Wr2 = (const float*)d_in[5];
    const float* b2  = (const float*)d_in[6];
    const float* Wl3 = (const float*)d_in[7];
    const float* Wr3 = (const float*)d_in[8];
    const float* b3  = (const float*)d_in[9];
    const void*  src1 = d_in[10];
    const void*  dst1 = d_in[11];
    const void*  src2 = d_in[12];
    const void*  src3 = d_in[14];
    float* out = (float*)d_out;

    __half *A1, *A2, *A3, *W1t, *W2t, *W3t, *h1, *h2;
    cudaGetSymbolAddress((void**)&A1, g_A1);
    cudaGetSymbolAddress((void**)&A2, g_A2);
    cudaGetSymbolAddress((void**)&A3, g_A3);
    cudaGetSymbolAddress((void**)&W1t, g_W1t);
    cudaGetSymbolAddress((void**)&W2t, g_W2t);
    cudaGetSymbolAddress((void**)&W3t, g_W3t);
    cudaGetSymbolAddress((void**)&h1, g_h1);
    cudaGetSymbolAddress((void**)&h2, g_h2);

    constexpr int SM1 = 3 * (128 + 128) * 80 + 128 * 4;  // 61952
    constexpr int SM2 = 3 * (64 + 64) * 80 + 64 * 4;     // 30976
    cudaFuncSetAttribute((const void*)mma_gemm<128, 128, 4, 2, K1P, true, false>,
                         cudaFuncAttributeMaxDynamicSharedMemorySize, SM1);
    cudaFuncSetAttribute((const void*)mma_gemm<64, 64, 2, 4, K2P, true, false>,
                         cudaFuncAttributeMaxDynamicSharedMemorySize, SM2);
    cudaFuncSetAttribute((const void*)mma_gemm<64, 64, 2, 4, K2P, false, true>,
                         cudaFuncAttributeMaxDynamicSharedMemorySize, SM2);

    // Side stream for pack_weights overlap (created once on the uncaptured
    // correctness call; identical work every call).
    static cudaStream_t s1 = nullptr;
    static cudaEvent_t evF = nullptr, evW = nullptr;
    if (s1 == nullptr) {
        cudaStreamCreateWithFlags(&s1, cudaStreamNonBlocking);
        cudaEventCreateWithFlags(&evF, cudaEventDisableTiming);
        cudaEventCreateWithFlags(&evW, cudaEventDisableTiming);
    }

    // Fork: pack_weights on s1, agg1 on stream 0 (independent — is64 is
    // derived inline from dst1 inside the gather kernels).
    cudaEventRecord(evF, 0);
    cudaStreamWaitEvent(s1, evF, 0);
    pack_weights<<<512, 256, 0, s1>>>(Wl1, Wr1, Wl2, Wr2, Wl3, Wr3);
    cudaEventRecord(evW, s1);

    agg1_kernel<<<kN1 / 8, 256>>>(x, src1, dst1);
    cudaStreamWaitEvent(0, evW, 0);  // join before gemm1 needs W1t

    mma_gemm<128, 128, 4, 2, K1P, true, false>
        <<<dim3(2, kN1 / 128), 256, SM1>>>(A1, W1t, b1, h1, 256);

    // layer 2 (BN=64 -> 384 CTAs)
    agg256_kernel<kFAN2><<<kN2 / 8, 256>>>(h1, src2, A2, kN2, dst1);
    mma_gemm<64, 64, 2, 4, K2P, true, false>
        <<<dim3(4, kN2 / 64), 256, SM2>>>(A2, W2t, b2, h2, 256);

    // layer 3 -> d_out logits
    agg256_kernel<kFAN3><<<kN3 / 8, 256>>>(h2, src3, A3, kN3, dst1);
    mma_gemm<64, 64, 2, 4, K2P, false, true>
        <<<dim3(1, kN3 / 64), 256, SM2>>>(A3, W3t, b3, out, kOUT);

    // log_softmax in place
    logsoftmax_kernel<<<kN3 / 8, 256>>>(out);
}